// round 15
// baseline (speedup 1.0000x reference)
#include <cuda_runtime.h>
#include <cuda_bf16.h>
#include <cstdint>

#define NPTS   65536
#define NGRAPH 16
#define K1     256      // x features only; pos(3) folded into epilogue
#define N1     256
#define N2     512
#define N3     1024

// ---------------- scratch (device globals; no allocations allowed) ----------
__device__ __nv_bfloat16 g_Xin[(size_t)NPTS * K1];   // [N][256] x as bf16
__device__ __nv_bfloat16 g_h1 [(size_t)NPTS * N1];
__device__ __nv_bfloat16 g_h2 [(size_t)NPTS * N2];
__device__ __nv_bfloat16 g_W1T[N1 * K1];             // [256][256]  W1[0:256]^T
__device__ __nv_bfloat16 g_W2T[N2 * N1];             // [512][256]
__device__ __nv_bfloat16 g_W3T[N3 * N2];             // [1024][512]
__device__ float g_pool[NGRAPH * N3];

// ---------------- helpers ----------------------------------------------------
__device__ __forceinline__ void mma16(float c[4], const uint32_t a[4], const uint32_t b[2]) {
    asm volatile(
        "mma.sync.aligned.m16n8k16.row.col.f32.bf16.bf16.f32 "
        "{%0,%1,%2,%3},{%4,%5,%6,%7},{%8,%9},{%0,%1,%2,%3};\n"
        : "+f"(c[0]), "+f"(c[1]), "+f"(c[2]), "+f"(c[3])
        : "r"(a[0]), "r"(a[1]), "r"(a[2]), "r"(a[3]),
          "r"(b[0]), "r"(b[1]));
}
__device__ __forceinline__ void ldsm4(uint32_t& d0, uint32_t& d1, uint32_t& d2, uint32_t& d3,
                                      uint32_t saddr) {
    asm volatile("ldmatrix.sync.aligned.m8n8.x4.shared.b16 {%0,%1,%2,%3}, [%4];"
                 : "=r"(d0), "=r"(d1), "=r"(d2), "=r"(d3) : "r"(saddr));
}
__device__ __forceinline__ void cpa16(uint32_t dst, const void* gmem) {
    asm volatile("cp.async.cg.shared.global [%0], [%1], 16;\n" :: "r"(dst), "l"(gmem));
}

// ---------------- merged prep: input pack + W transposes + pool init ----------
#define PX (NPTS * 32)            // 2097152 uint4 stores
#define P1 (N1 * K1)              // 65536
#define P2 (P1 + N2 * N1)         // +131072
#define P3 (P2 + N3 * N2)         // +524288
#define PT (P3 + NGRAPH * N3)     // +16384
#define PALL (PX + PT)
__global__ void prep_all(const float4* __restrict__ x,
                         const float* __restrict__ W1, const float* __restrict__ W2,
                         const float* __restrict__ W3) {
    int idx = blockIdx.x * blockDim.x + threadIdx.x;
    if (idx < PX) {
        float4 a = x[2 * idx];
        float4 b = x[2 * idx + 1];
        __nv_bfloat16 v[8];
        v[0] = __float2bfloat16(a.x); v[1] = __float2bfloat16(a.y);
        v[2] = __float2bfloat16(a.z); v[3] = __float2bfloat16(a.w);
        v[4] = __float2bfloat16(b.x); v[5] = __float2bfloat16(b.y);
        v[6] = __float2bfloat16(b.z); v[7] = __float2bfloat16(b.w);
        reinterpret_cast<uint4*>(g_Xin)[idx] = *reinterpret_cast<uint4*>(v);
        return;
    }
    idx -= PX;
    if (idx < P1) {
        int n = idx >> 8, k = idx & 255;          // K1 = 256
        g_W1T[idx] = __float2bfloat16(W1[k * N1 + n]);
    } else if (idx < P2) {
        int j = idx - P1;
        int n = j / N1, k = j - n * N1;
        g_W2T[j] = __float2bfloat16(W2[k * N2 + n]);
    } else if (idx < P3) {
        int j = idx - P2;
        int n = j / N2, k = j - n * N2;
        g_W3T[j] = __float2bfloat16(W3[k * N3 + n]);
    } else if (idx < PT) {
        g_pool[idx - P3] = 0.f;    // relu output >= 0
    }
}

// ---------------- layers 1&2: persistent-B GEMM + bias + relu -----------------
// K=256 for both layers. Each CTA: col block of 128 (B [128][256] = 64KB held
// entirely in smem, 4 swizzled subtiles) x 2 row tiles of 128 (A double-buffer
// 2x16KB). 8 chunks per CTA amortize prologue/epilogue like GEMM3.
// 256 threads = 8 warps (2M x 4N), warp tile 64x32, 2 CTAs/SM, 96KB smem.
template<int LAYER>
__global__ void __launch_bounds__(256, 2)
gemm12(const float* __restrict__ bias, const float* __restrict__ posp,
       const float* __restrict__ W1raw) {
    constexpr int Nd = (LAYER == 1) ? N1 : N2;
    constexpr int T  = 8;                     // 2 row tiles x 4 chunks

    const __nv_bfloat16* __restrict__ A  = (LAYER == 1) ? g_Xin : g_h1;
    const __nv_bfloat16* __restrict__ Bw = (LAYER == 1) ? g_W1T : g_W2T;
    __nv_bfloat16* __restrict__ Cc       = (LAYER == 1) ? g_h1 : g_h2;

    extern __shared__ __align__(1024) char smem[];
    const uint32_t sbase = (uint32_t)__cvta_generic_to_shared(smem);
    const uint32_t sBb = sbase;               // 4 x 16KB B subtiles
    const uint32_t sAb = sbase + 65536;       // 2 x 16KB A stages

    const int tid = threadIdx.x;
    const int rowBase = blockIdx.y * 256;     // 2 row tiles per CTA
    const int colBase = blockIdx.x * 128;

    {   // whole B col block: subtile c holds k in [64c, 64c+64), swizzled rows
        const __nv_bfloat16* srcB = Bw + (size_t)colBase * 256;
#pragma unroll
        for (int i = 0; i < 16; i++) {
            int seg = tid + i * 256;          // 0..4095
            int sub = seg >> 10, rem = seg & 1023;
            int r = rem >> 3, kq = rem & 7;
            int sw = kq ^ (r & 7);
            cpa16(sBb + sub * 16384 + r * 128 + sw * 16,
                  srcB + (size_t)r * 256 + sub * 64 + kq * 8);
        }
        asm volatile("cp.async.commit_group;\n");
    }
    auto load_A = [&](int s, int t) {
        const __nv_bfloat16* srcA =
            A + (size_t)(rowBase + (t >> 2) * 128) * 256 + (t & 3) * 64;
#pragma unroll
        for (int i = 0; i < 4; i++) {
            int seg = tid + i * 256;
            int r = seg >> 3, kq = seg & 7;
            int sw = kq ^ (r & 7);
            cpa16(sAb + s * 16384 + r * 128 + sw * 16,
                  srcA + (size_t)r * 256 + kq * 8);
        }
        asm volatile("cp.async.commit_group;\n");
    };

    const int warp = tid >> 5, lane = tid & 31;
    const int wM = warp & 1, wN = warp >> 1;     // 2 x 4
    const int g  = lane >> 2, tg = lane & 3;

    const int aRow = wM * 64 + (lane & 7) + ((lane >> 3) & 1) * 8;
    const int aC0  = (lane >> 4) & 1;
    const int aSw  = aRow & 7;
    const int bRow = wN * 32 + (lane & 7) + ((lane >> 4) & 1) * 8;
    const int bC0  = (lane >> 3) & 1;
    const int bSw  = bRow & 7;

    float acc[4][4][4];
#pragma unroll
    for (int a = 0; a < 4; a++)
#pragma unroll
        for (int b = 0; b < 4; b++)
#pragma unroll
            for (int e = 0; e < 4; e++) acc[a][b][e] = 0.f;

    uint32_t af[2][4][4], bf[2][4][2];

    auto ldfragA = [&](int buf, int ks, uint32_t aBase) {
        const uint32_t ko = ((uint32_t)((2 * ks + aC0) ^ aSw)) << 4;
#pragma unroll
        for (int mt = 0; mt < 4; mt++)
            ldsm4(af[buf][mt][0], af[buf][mt][1], af[buf][mt][2], af[buf][mt][3],
                  aBase + (uint32_t)(aRow + mt * 16) * 128 + ko);
    };
    auto ldfragB = [&](int buf, int ks, uint32_t bBase) {
        const uint32_t ko = ((uint32_t)((2 * ks + bC0) ^ bSw)) << 4;
#pragma unroll
        for (int np = 0; np < 2; np++)
            ldsm4(bf[buf][2 * np][0], bf[buf][2 * np][1],
                  bf[buf][2 * np + 1][0], bf[buf][2 * np + 1][1],
                  bBase + (uint32_t)(bRow + np * 16) * 128 + ko);
    };

    auto epilogue = [&](int rBase2) {
        if (LAYER == 1) {
            // exact fp32 rank-3 correction: acc += pos[row] . W1[256:259][col]
#pragma unroll
            for (int nt = 0; nt < 4; nt++) {
                int c0 = colBase + wN * 32 + nt * 8 + tg * 2;
                float wa[3], wb[3];
#pragma unroll
                for (int j = 0; j < 3; j++) {
                    wa[j] = W1raw[(256 + j) * N1 + c0];
                    wb[j] = W1raw[(256 + j) * N1 + c0 + 1];
                }
#pragma unroll
                for (int mt = 0; mt < 4; mt++) {
                    int r0 = rBase2 + wM * 64 + mt * 16 + g;
                    const float* p0 = posp + 3 * (size_t)r0;
                    const float* p1 = posp + 3 * (size_t)(r0 + 8);
                    acc[mt][nt][0] += p0[0] * wa[0] + p0[1] * wa[1] + p0[2] * wa[2];
                    acc[mt][nt][1] += p0[0] * wb[0] + p0[1] * wb[1] + p0[2] * wb[2];
                    acc[mt][nt][2] += p1[0] * wa[0] + p1[1] * wa[1] + p1[2] * wa[2];
                    acc[mt][nt][3] += p1[0] * wb[0] + p1[1] * wb[1] + p1[2] * wb[2];
                }
            }
        }
#pragma unroll
        for (int nt = 0; nt < 4; nt++) {
            int c0 = colBase + wN * 32 + nt * 8 + tg * 2;
            float b0 = bias[c0], b1v = bias[c0 + 1];
#pragma unroll
            for (int mt = 0; mt < 4; mt++) {
                int r0 = rBase2 + wM * 64 + mt * 16 + g;
                __nv_bfloat162 h0 = __floats2bfloat162_rn(
                    fmaxf(acc[mt][nt][0] + b0,  0.f),
                    fmaxf(acc[mt][nt][1] + b1v, 0.f));
                *reinterpret_cast<uint32_t*>(&Cc[(size_t)r0 * Nd + c0]) =
                    *reinterpret_cast<uint32_t*>(&h0);
                __nv_bfloat162 h1 = __floats2bfloat162_rn(
                    fmaxf(acc[mt][nt][2] + b0,  0.f),
                    fmaxf(acc[mt][nt][3] + b1v, 0.f));
                *reinterpret_cast<uint32_t*>(&Cc[(size_t)(r0 + 8) * Nd + c0]) =
                    *reinterpret_cast<uint32_t*>(&h1);
            }
        }
        // reset accumulators for the next row tile
#pragma unroll
        for (int a = 0; a < 4; a++)
#pragma unroll
            for (int b = 0; b < 4; b++)
#pragma unroll
                for (int e = 0; e < 4; e++) acc[a][b][e] = 0.f;
    };

    load_A(0, 0);

    for (int t = 0; t < T; t++) {
        const int cur = t & 1;
        if (t + 1 < T) {
            load_A(cur ^ 1, t + 1);
            asm volatile("cp.async.wait_group 1;\n" ::: "memory");
        } else {
            asm volatile("cp.async.wait_group 0;\n" ::: "memory");
        }
        __syncthreads();

        const uint32_t aBase = sAb + (uint32_t)cur * 16384;
        const uint32_t bBase = sBb + (uint32_t)(t & 3) * 16384;

        ldfragA(0, 0, aBase);
        ldfragB(0, 0, bBase);
#pragma unroll
        for (int ks = 0; ks < 4; ks++) {
            const int cb = ks & 1, nb = cb ^ 1;
            if (ks < 3) { ldfragA(nb, ks + 1, aBase); ldfragB(nb, ks + 1, bBase); }
#pragma unroll
            for (int mt = 0; mt < 4; mt++)
#pragma unroll
                for (int nt = 0; nt < 4; nt++)
                    mma16(acc[mt][nt], af[cb][mt], bf[cb][nt]);
        }
        __syncthreads();

        if ((t & 3) == 3)
            epilogue(rowBase + (t >> 2) * 128);
    }
}

// ---------------- layer 3 GEMM + fused segment-max + x_skip copy --------------
// Identical to the R14 winner: CTA 128x128, BK=64, grid x=colBlock y=rowTile.
__global__ void __launch_bounds__(256, 2)
gemm3(const float* __restrict__ bias, const int* __restrict__ batch,
      const float4* __restrict__ x_skip, float4* __restrict__ outp) {
    constexpr int Kd = N2, NC = Kd / 64;

    const __nv_bfloat16* __restrict__ A  = g_h2;
    const __nv_bfloat16* __restrict__ Bw = g_W3T;

    extern __shared__ __align__(1024) char smem[];
    const uint32_t sbase = (uint32_t)__cvta_generic_to_shared(smem);
    constexpr uint32_t STG = 32768;

    const int tid = threadIdx.x;
    const int rowBase = blockIdx.y * 128;
    const int colBase = blockIdx.x * 128;

    auto load_stage = [&](int s, int kc) {
        const uint32_t dA = sbase + s * STG;
        const uint32_t dB = dA + 16384;
        const __nv_bfloat16* srcA = A + (size_t)rowBase * Kd + kc * 64;
        const __nv_bfloat16* srcB = Bw + (size_t)colBase * Kd + kc * 64;
#pragma unroll
        for (int i = 0; i < 4; i++) {
            int seg = tid + i * 256;
            int r = seg >> 3, kq = seg & 7;
            int sw = kq ^ (r & 7);
            cpa16(dA + r * 128 + sw * 16, srcA + (size_t)r * Kd + kq * 8);
        }
#pragma unroll
        for (int i = 0; i < 4; i++) {
            int seg = tid + i * 256;
            int r = seg >> 3, kq = seg & 7;
            int sw = kq ^ (r & 7);
            cpa16(dB + r * 128 + sw * 16, srcB + (size_t)r * Kd + kq * 8);
        }
        asm volatile("cp.async.commit_group;\n");
    };

    const int warp = tid >> 5, lane = tid & 31;
    const int wM = warp & 1, wN = warp >> 1;
    const int g  = lane >> 2, tg = lane & 3;

    const int aRow = wM * 64 + (lane & 7) + ((lane >> 3) & 1) * 8;
    const int aC0  = (lane >> 4) & 1;
    const int aSw  = aRow & 7;
    const int bRow = wN * 32 + (lane & 7) + ((lane >> 4) & 1) * 8;
    const int bC0  = (lane >> 3) & 1;
    const int bSw  = bRow & 7;

    float acc[4][4][4];
#pragma unroll
    for (int a = 0; a < 4; a++)
#pragma unroll
        for (int b = 0; b < 4; b++)
#pragma unroll
            for (int e = 0; e < 4; e++) acc[a][b][e] = 0.f;

    uint32_t af[2][4][4], bf[2][4][2];

    auto ldfragA = [&](int buf, int ks, uint32_t aBase) {
        const uint32_t ko = ((uint32_t)((2 * ks + aC0) ^ aSw)) << 4;
#pragma unroll
        for (int mt = 0; mt < 4; mt++)
            ldsm4(af[buf][mt][0], af[buf][mt][1], af[buf][mt][2], af[buf][mt][3],
                  aBase + (uint32_t)(aRow + mt * 16) * 128 + ko);
    };
    auto ldfragB = [&](int buf, int ks, uint32_t bBase) {
        const uint32_t ko = ((uint32_t)((2 * ks + bC0) ^ bSw)) << 4;
#pragma unroll
        for (int np = 0; np < 2; np++)
            ldsm4(bf[buf][2 * np][0], bf[buf][2 * np][1],
                  bf[buf][2 * np + 1][0], bf[buf][2 * np + 1][1],
                  bBase + (uint32_t)(bRow + np * 16) * 128 + ko);
    };

    load_stage(0, 0);

    for (int c = 0; c < NC; c++) {
        int cur = c & 1;
        if (c + 1 < NC) {
            load_stage(cur ^ 1, c + 1);
            asm volatile("cp.async.wait_group 1;\n" ::: "memory");
        } else {
            asm volatile("cp.async.wait_group 0;\n" ::: "memory");
        }
        __syncthreads();

        const uint32_t aBase = sbase + cur * STG;
        const uint32_t bBase = aBase + 16384;

        ldfragA(0, 0, aBase);
        ldfragB(0, 0, bBase);
#pragma unroll
        for (int ks = 0; ks < 4; ks++) {
            const int cb = ks & 1, nb = cb ^ 1;
            if (ks < 3) { ldfragA(nb, ks + 1, aBase); ldfragB(nb, ks + 1, bBase); }
#pragma unroll
            for (int mt = 0; mt < 4; mt++)
#pragma unroll
                for (int nt = 0; nt < 4; nt++)
                    mma16(acc[mt][nt], af[cb][mt], bf[cb][nt]);
        }
        __syncthreads();
    }

    // fused: relu + per-column max over this CTA's 128 rows -> atomicMax
    int gr = batch[rowBase];
#pragma unroll
    for (int nt = 0; nt < 4; nt++) {
#pragma unroll
        for (int j = 0; j < 2; j++) {
            int col = colBase + wN * 32 + nt * 8 + tg * 2 + j;
            float m = acc[0][nt][j];
#pragma unroll
            for (int mt = 0; mt < 4; mt++)
                m = fmaxf(m, fmaxf(acc[mt][nt][j], acc[mt][nt][j + 2]));
            m = fmaxf(m + bias[col], 0.f);
            m = fmaxf(m, __shfl_xor_sync(0xffffffffu, m, 4));
            m = fmaxf(m, __shfl_xor_sync(0xffffffffu, m, 8));
            m = fmaxf(m, __shfl_xor_sync(0xffffffffu, m, 16));
            if (g == 0)   // nonneg floats: int compare == float compare
                atomicMax(reinterpret_cast<int*>(&g_pool[gr * N3 + col]),
                          __float_as_int(m));
        }
    }
    // x_skip half of the final output: out[r][1024:1280) = x_skip[r].
    {
        const int rSlab = rowBase + (int)blockIdx.x * 16;   // grid.x = 8
#pragma unroll
        for (int i = 0; i < 4; i++) {
            int idx = tid + i * 256;                        // 1024 = 16 x 64
            int r = rSlab + (idx >> 6), q = idx & 63;
            float4 v = __ldcs(&x_skip[(size_t)r * 64 + q]);
            __stcs(&outp[(size_t)r * 320 + 256 + q], v);
        }
    }
}

// ---------------- output (pooled half): out[n][0:1024) = pooled[batch_skip[n]]
__global__ void out_kernel(const int* __restrict__ batch_skip,
                           float4* __restrict__ out) {
    int n = blockIdx.x;
    int q = threadIdx.x;              // 256 float4 = 1024 floats
    int gr = batch_skip[n];
    float4 v = reinterpret_cast<const float4*>(g_pool)[gr * 256 + q];
    __stcs(&out[(size_t)n * 320 + q], v);
}

// ---------------- launcher -----------------------------------------------------
extern "C" void kernel_launch(void* const* d_in, const int* in_sizes, int n_in,
                              void* d_out, int out_size) {
    const float* x          = (const float*)d_in[0];
    const float* pos        = (const float*)d_in[1];
    const int*   batch      = (const int*)  d_in[2];
    const float* x_skip     = (const float*)d_in[3];
    /* pos_skip d_in[4]: interpolation weights cancel exactly, unused */
    const int*   batch_skip = (const int*)  d_in[5];
    const float* W1 = (const float*)d_in[6];
    const float* b1 = (const float*)d_in[7];
    const float* W2 = (const float*)d_in[8];
    const float* b2 = (const float*)d_in[9];
    const float* W3 = (const float*)d_in[10];
    const float* b3 = (const float*)d_in[11];

    const int SMEM12 = 98304;   // 64KB B + 2 x 16KB A
    const int SMEM3  = 65536;   // 2 stages x (16KB A + 16KB B)
    cudaFuncSetAttribute(gemm12<1>, cudaFuncAttributeMaxDynamicSharedMemorySize, SMEM12);
    cudaFuncSetAttribute(gemm12<2>, cudaFuncAttributeMaxDynamicSharedMemorySize, SMEM12);
    cudaFuncSetAttribute(gemm3, cudaFuncAttributeMaxDynamicSharedMemorySize, SMEM3);

    prep_all<<<(PALL + 255) / 256, 256>>>((const float4*)x, W1, W2, W3);

    gemm12<1><<<dim3(N1 / 128, NPTS / 256), 256, SMEM12>>>(b1, pos, W1);
    gemm12<2><<<dim3(N2 / 128, NPTS / 256), 256, SMEM12>>>(b2, nullptr, nullptr);
    gemm3<<<dim3(N3 / 128, NPTS / 128), 256, SMEM3>>>(
        b3, batch, (const float4*)x_skip, (float4*)d_out);

    out_kernel<<<NPTS, 256>>>(batch_skip, (float4*)d_out);
}

// round 16
// speedup vs baseline: 1.0801x; 1.0801x over previous
#include <cuda_runtime.h>
#include <cuda_bf16.h>
#include <cstdint>

#define NPTS   65536
#define NGRAPH 16
#define K1     256      // x features only; pos(3) folded into epilogue
#define N1     256
#define N2     512
#define N3     1024

// ---------------- scratch (device globals; no allocations allowed) ----------
__device__ __nv_bfloat16 g_Xin[(size_t)NPTS * K1];   // [N][256] x as bf16
__device__ __nv_bfloat16 g_h1 [(size_t)NPTS * N1];
__device__ __nv_bfloat16 g_h2 [(size_t)NPTS * N2];
__device__ __nv_bfloat16 g_W1T[N1 * K1];             // [256][256]  W1[0:256]^T
__device__ __nv_bfloat16 g_W2T[N2 * N1];             // [512][256]
__device__ __nv_bfloat16 g_W3T[N3 * N2];             // [1024][512]
__device__ float g_pool[NGRAPH * N3];

// ---------------- helpers ----------------------------------------------------
__device__ __forceinline__ void mma16(float c[4], const uint32_t a[4], const uint32_t b[2]) {
    asm volatile(
        "mma.sync.aligned.m16n8k16.row.col.f32.bf16.bf16.f32 "
        "{%0,%1,%2,%3},{%4,%5,%6,%7},{%8,%9},{%0,%1,%2,%3};\n"
        : "+f"(c[0]), "+f"(c[1]), "+f"(c[2]), "+f"(c[3])
        : "r"(a[0]), "r"(a[1]), "r"(a[2]), "r"(a[3]),
          "r"(b[0]), "r"(b[1]));
}
__device__ __forceinline__ void ldsm4(uint32_t& d0, uint32_t& d1, uint32_t& d2, uint32_t& d3,
                                      uint32_t saddr) {
    asm volatile("ldmatrix.sync.aligned.m8n8.x4.shared.b16 {%0,%1,%2,%3}, [%4];"
                 : "=r"(d0), "=r"(d1), "=r"(d2), "=r"(d3) : "r"(saddr));
}
__device__ __forceinline__ void cpa16(uint32_t dst, const void* gmem) {
    asm volatile("cp.async.cg.shared.global [%0], [%1], 16;\n" :: "r"(dst), "l"(gmem));
}

// ---------------- merged prep: input pack + W transposes + pool init ----------
#define PX (NPTS * 32)            // 2097152 uint4 stores
#define P1 (N1 * K1)              // 65536
#define P2 (P1 + N2 * N1)         // +131072
#define P3 (P2 + N3 * N2)         // +524288
#define PT (P3 + NGRAPH * N3)     // +16384
#define PALL (PX + PT)
__global__ void prep_all(const float4* __restrict__ x,
                         const float* __restrict__ W1, const float* __restrict__ W2,
                         const float* __restrict__ W3) {
    int idx = blockIdx.x * blockDim.x + threadIdx.x;
    if (idx < PX) {
        float4 a = x[2 * idx];
        float4 b = x[2 * idx + 1];
        __nv_bfloat16 v[8];
        v[0] = __float2bfloat16(a.x); v[1] = __float2bfloat16(a.y);
        v[2] = __float2bfloat16(a.z); v[3] = __float2bfloat16(a.w);
        v[4] = __float2bfloat16(b.x); v[5] = __float2bfloat16(b.y);
        v[6] = __float2bfloat16(b.z); v[7] = __float2bfloat16(b.w);
        reinterpret_cast<uint4*>(g_Xin)[idx] = *reinterpret_cast<uint4*>(v);
        return;
    }
    idx -= PX;
    if (idx < P1) {
        int n = idx >> 8, k = idx & 255;          // K1 = 256
        g_W1T[idx] = __float2bfloat16(W1[k * N1 + n]);
    } else if (idx < P2) {
        int j = idx - P1;
        int n = j / N1, k = j - n * N1;
        g_W2T[j] = __float2bfloat16(W2[k * N2 + n]);
    } else if (idx < P3) {
        int j = idx - P2;
        int n = j / N2, k = j - n * N2;
        g_W3T[j] = __float2bfloat16(W3[k * N3 + n]);
    } else if (idx < PT) {
        g_pool[idx - P3] = 0.f;    // relu output >= 0
    }
}

// ---------------- bf16 GEMM + relu (+ fused segment-max pooling for layer 3) --
// CTA tile 128x128, BK=64, 256 threads = 8 warps (2M x 4N), warp tile 64x32.
// XOR-swizzled smem, cp.async double buffered, fragment double buffering,
// 2 CTAs/SM. Grid: x = colBlock (few), y = rowTile (many) -> consecutive CTAs
// share the same A tile, so A hits L2 once per colBlock sweep.
// Layer 1: exact fp32 rank-3 pos correction in epilogue.
// Layer 3: fused segment-max + x_skip half of the output copy.
template<int LAYER>
__global__ void __launch_bounds__(256, 2)
gemm_relu(const float* __restrict__ bias, const int* __restrict__ batch,
          const float* __restrict__ posp, const float* __restrict__ W1raw,
          const float4* __restrict__ x_skip, float4* __restrict__ outp) {
    constexpr int Kd   = (LAYER == 1) ? K1 : ((LAYER == 2) ? N1 : N2);
    constexpr int Nd   = (LAYER == 1) ? N1 : ((LAYER == 2) ? N2 : N3);
    constexpr bool POOL = (LAYER == 3);
    constexpr int NC   = Kd / 64;

    const __nv_bfloat16* __restrict__ A =
        (LAYER == 1) ? g_Xin : ((LAYER == 2) ? g_h1 : g_h2);
    const __nv_bfloat16* __restrict__ Bw =
        (LAYER == 1) ? g_W1T : ((LAYER == 2) ? g_W2T : g_W3T);
    __nv_bfloat16* __restrict__ Cc = (LAYER == 1) ? g_h1 : g_h2;

    // dynamic smem: stage s at s*32KB; A tile [128][64] at +0, B tile at +16KB
    extern __shared__ __align__(1024) char smem[];
    const uint32_t sbase = (uint32_t)__cvta_generic_to_shared(smem);
    constexpr uint32_t STG = 32768;

    const int tid = threadIdx.x;
    const int rowBase = blockIdx.y * 128;     // y = rowTile (x-fastest sched)
    const int colBase = blockIdx.x * 128;     // x = colBlock

    auto load_stage = [&](int s, int kc) {
        const uint32_t dA = sbase + s * STG;
        const uint32_t dB = dA + 16384;
        const __nv_bfloat16* srcA = A + (size_t)rowBase * Kd + kc * 64;
        const __nv_bfloat16* srcB = Bw + (size_t)colBase * Kd + kc * 64;
#pragma unroll
        for (int i = 0; i < 4; i++) {          // A: 128 rows x 8 chunks of 16B
            int seg = tid + i * 256;
            int r = seg >> 3, kq = seg & 7;
            int sw = kq ^ (r & 7);
            cpa16(dA + r * 128 + sw * 16, srcA + (size_t)r * Kd + kq * 8);
        }
#pragma unroll
        for (int i = 0; i < 4; i++) {          // B: 128 n-rows x 8 chunks
            int seg = tid + i * 256;
            int r = seg >> 3, kq = seg & 7;
            int sw = kq ^ (r & 7);
            cpa16(dB + r * 128 + sw * 16, srcB + (size_t)r * Kd + kq * 8);
        }
        asm volatile("cp.async.commit_group;\n");
    };

    const int warp = tid >> 5, lane = tid & 31;
    const int wM = warp & 1, wN = warp >> 1;     // 2 x 4
    const int g  = lane >> 2, tg = lane & 3;

    // per-lane ldmatrix coordinates (row within tile, base chunk parity)
    const int aRow = wM * 64 + (lane & 7) + ((lane >> 3) & 1) * 8;
    const int aC0  = (lane >> 4) & 1;            // k half (0/8) -> chunk bit 0
    const int aSw  = aRow & 7;
    const int bRow = wN * 32 + (lane & 7) + ((lane >> 4) & 1) * 8;
    const int bC0  = (lane >> 3) & 1;
    const int bSw  = bRow & 7;

    float acc[4][4][4];
#pragma unroll
    for (int a = 0; a < 4; a++)
#pragma unroll
        for (int b = 0; b < 4; b++)
#pragma unroll
            for (int e = 0; e < 4; e++) acc[a][b][e] = 0.f;

    uint32_t af[2][4][4], bf[2][4][2];

    auto ldfragA = [&](int buf, int ks, uint32_t aBase) {
        const uint32_t ko = ((uint32_t)((2 * ks + aC0) ^ aSw)) << 4;
#pragma unroll
        for (int mt = 0; mt < 4; mt++)
            ldsm4(af[buf][mt][0], af[buf][mt][1], af[buf][mt][2], af[buf][mt][3],
                  aBase + (uint32_t)(aRow + mt * 16) * 128 + ko);
    };
    auto ldfragB = [&](int buf, int ks, uint32_t bBase) {
        const uint32_t ko = ((uint32_t)((2 * ks + bC0) ^ bSw)) << 4;
#pragma unroll
        for (int np = 0; np < 2; np++)
            ldsm4(bf[buf][2 * np][0], bf[buf][2 * np][1],
                  bf[buf][2 * np + 1][0], bf[buf][2 * np + 1][1],
                  bBase + (uint32_t)(bRow + np * 16) * 128 + ko);
    };

    load_stage(0, 0);

    for (int c = 0; c < NC; c++) {
        int cur = c & 1;
        if (c + 1 < NC) {
            load_stage(cur ^ 1, c + 1);
            asm volatile("cp.async.wait_group 1;\n");
        } else {
            asm volatile("cp.async.wait_group 0;\n");
        }
        __syncthreads();

        const uint32_t aBase = sbase + cur * STG;
        const uint32_t bBase = aBase + 16384;

        ldfragA(0, 0, aBase);
        ldfragB(0, 0, bBase);
#pragma unroll
        for (int ks = 0; ks < 4; ks++) {       // four k16 steps per BK=64
            const int cb = ks & 1, nb = cb ^ 1;
            if (ks < 3) { ldfragA(nb, ks + 1, aBase); ldfragB(nb, ks + 1, bBase); }
#pragma unroll
            for (int mt = 0; mt < 4; mt++)
#pragma unroll
                for (int nt = 0; nt < 4; nt++)
                    mma16(acc[mt][nt], af[cb][mt], bf[cb][nt]);
        }
        __syncthreads();
    }

    if (!POOL) {
        if (LAYER == 1) {
            // exact fp32 rank-3 correction: acc += pos[row] . W1[256:259][col]
#pragma unroll
            for (int nt = 0; nt < 4; nt++) {
                int c0 = colBase + wN * 32 + nt * 8 + tg * 2;
                float wa[3], wb[3];
#pragma unroll
                for (int j = 0; j < 3; j++) {
                    wa[j] = W1raw[(256 + j) * N1 + c0];
                    wb[j] = W1raw[(256 + j) * N1 + c0 + 1];
                }
#pragma unroll
                for (int mt = 0; mt < 4; mt++) {
                    int r0 = rowBase + wM * 64 + mt * 16 + g;
                    const float* p0 = posp + 3 * (size_t)r0;
                    const float* p1 = posp + 3 * (size_t)(r0 + 8);
                    acc[mt][nt][0] += p0[0] * wa[0] + p0[1] * wa[1] + p0[2] * wa[2];
                    acc[mt][nt][1] += p0[0] * wb[0] + p0[1] * wb[1] + p0[2] * wb[2];
                    acc[mt][nt][2] += p1[0] * wa[0] + p1[1] * wa[1] + p1[2] * wa[2];
                    acc[mt][nt][3] += p1[0] * wb[0] + p1[1] * wb[1] + p1[2] * wb[2];
                }
            }
        }
#pragma unroll
        for (int nt = 0; nt < 4; nt++) {
            int c0 = colBase + wN * 32 + nt * 8 + tg * 2;
            float b0 = bias[c0], b1v = bias[c0 + 1];
#pragma unroll
            for (int mt = 0; mt < 4; mt++) {
                int r0 = rowBase + wM * 64 + mt * 16 + g;
                __nv_bfloat162 h0 = __floats2bfloat162_rn(
                    fmaxf(acc[mt][nt][0] + b0,  0.f),
                    fmaxf(acc[mt][nt][1] + b1v, 0.f));
                *reinterpret_cast<uint32_t*>(&Cc[(size_t)r0 * Nd + c0]) =
                    *reinterpret_cast<uint32_t*>(&h0);
                __nv_bfloat162 h1 = __floats2bfloat162_rn(
                    fmaxf(acc[mt][nt][2] + b0,  0.f),
                    fmaxf(acc[mt][nt][3] + b1v, 0.f));
                *reinterpret_cast<uint32_t*>(&Cc[(size_t)(r0 + 8) * Nd + c0]) =
                    *reinterpret_cast<uint32_t*>(&h1);
            }
        }
    } else {
        // fused: relu + per-column max over this CTA's 128 rows -> atomicMax
        int gr = batch[rowBase];   // 128-row tile lies within one graph
#pragma unroll
        for (int nt = 0; nt < 4; nt++) {
#pragma unroll
            for (int j = 0; j < 2; j++) {
                int col = colBase + wN * 32 + nt * 8 + tg * 2 + j;
                float m = acc[0][nt][j];
#pragma unroll
                for (int mt = 0; mt < 4; mt++)
                    m = fmaxf(m, fmaxf(acc[mt][nt][j], acc[mt][nt][j + 2]));
                m = fmaxf(m + bias[col], 0.f);
                m = fmaxf(m, __shfl_xor_sync(0xffffffffu, m, 4));
                m = fmaxf(m, __shfl_xor_sync(0xffffffffu, m, 8));
                m = fmaxf(m, __shfl_xor_sync(0xffffffffu, m, 16));
                if (g == 0)   // nonneg floats: int compare == float compare
                    atomicMax(reinterpret_cast<int*>(&g_pool[gr * N3 + col]),
                              __float_as_int(m));
            }
        }
        // x_skip half of the final output: out[r][1024:1280) = x_skip[r].
        // Disjoint 16-row slab per (colBlock, rowTile) CTA; streaming stores
        // overlap other CTAs' mainloops across GEMM3's many waves.
        {
            const int rSlab = rowBase + (int)blockIdx.x * 16;   // grid.x = 8
#pragma unroll
            for (int i = 0; i < 4; i++) {
                int idx = tid + i * 256;                        // 1024 = 16 x 64
                int r = rSlab + (idx >> 6), q = idx & 63;
                float4 v = __ldcs(&x_skip[(size_t)r * 64 + q]);
                __stcs(&outp[(size_t)r * 320 + 256 + q], v);
            }
        }
    }
}

// ---------------- output (pooled half): out[n][0:1024) = pooled[batch_skip[n]]
// coarsened: 8 rows per 256-thread block (pool stays L1-hot within a block)
__global__ void out_kernel(const int* __restrict__ batch_skip,
                           float4* __restrict__ out) {
    const int n0 = blockIdx.x * 8;
    const int q  = threadIdx.x;       // 256 float4 = 1024 floats
#pragma unroll
    for (int i = 0; i < 8; i++) {
        int n = n0 + i;
        int gr = batch_skip[n];
        float4 v = reinterpret_cast<const float4*>(g_pool)[gr * 256 + q];
        __stcs(&out[(size_t)n * 320 + q], v);
    }
}

// ---------------- launcher -----------------------------------------------------
extern "C" void kernel_launch(void* const* d_in, const int* in_sizes, int n_in,
                              void* d_out, int out_size) {
    const float* x          = (const float*)d_in[0];
    const float* pos        = (const float*)d_in[1];
    const int*   batch      = (const int*)  d_in[2];
    const float* x_skip     = (const float*)d_in[3];
    /* pos_skip d_in[4]: interpolation weights cancel exactly, unused */
    const int*   batch_skip = (const int*)  d_in[5];
    const float* W1 = (const float*)d_in[6];
    const float* b1 = (const float*)d_in[7];
    const float* W2 = (const float*)d_in[8];
    const float* b2 = (const float*)d_in[9];
    const float* W3 = (const float*)d_in[10];
    const float* b3 = (const float*)d_in[11];

    const int SMEM = 65536;   // 2 stages x (16KB A + 16KB B)
    cudaFuncSetAttribute(gemm_relu<1>, cudaFuncAttributeMaxDynamicSharedMemorySize, SMEM);
    cudaFuncSetAttribute(gemm_relu<2>, cudaFuncAttributeMaxDynamicSharedMemorySize, SMEM);
    cudaFuncSetAttribute(gemm_relu<3>, cudaFuncAttributeMaxDynamicSharedMemorySize, SMEM);

    prep_all<<<(PALL + 255) / 256, 256>>>((const float4*)x, W1, W2, W3);

    gemm_relu<1><<<dim3(N1 / 128, NPTS / 128), 256, SMEM>>>(
        b1, nullptr, pos, W1, nullptr, nullptr);
    gemm_relu<2><<<dim3(N2 / 128, NPTS / 128), 256, SMEM>>>(
        b2, nullptr, nullptr, nullptr, nullptr, nullptr);
    gemm_relu<3><<<dim3(N3 / 128, NPTS / 128), 256, SMEM>>>(
        b3, batch, nullptr, nullptr, (const float4*)x_skip, (float4*)d_out);

    out_kernel<<<NPTS / 8, 256>>>(batch_skip, (float4*)d_out);
}